// round 9
// baseline (speedup 1.0000x reference)
#include <cuda_runtime.h>
#include <math.h>
#include <stdint.h>

#define NN 100000
#define NE 1600000
#define ETOT (NE + NN)
#define HD192 192
#define D64 64
#define HD63 63
#define D21 21
#define NG 8
#define NCLS 10
#define EPSBN 1e-5f
#define SBLK 98          // scan blocks: 98 * 1024 >= NN

// ---------------- scratch (device globals; no allocs allowed) ----------------
__device__ float g_xl[(size_t)NN * HD192];
__device__ float g_xr[(size_t)NN * HD192];
__device__ float g_h[(size_t)NN * HD192];
__device__ float g_h2[(size_t)NN * D64];
__device__ int   g_counts[NN];
__device__ int   g_rowptr[NN + 1];
__device__ int   g_cursor[NN];
__device__ int   g_col[ETOT];
__device__ int   g_bsum[SBLK];
__device__ int   g_boff[SBLK];
__device__ float g_bnsum[HD192];
__device__ float g_bnsq[HD192];
__device__ float g_bnscale[HD192];
__device__ float g_bnshift[HD192];
__device__ float g_pool[NG * D64];
__device__ float g_cnt[NG];

// ---------------- small resets ----------------
__global__ void reset_small_kernel() {
    int t = threadIdx.x;
    if (t < HD192) { g_bnsum[t] = 0.f; g_bnsq[t] = 0.f; }
    if (t < NG * D64) g_pool[t] = 0.f;
    if (t < NG) g_cnt[t] = 0.f;
}

// ---------------- CSR build ----------------
__global__ void init_counts_kernel() {
    int i = blockIdx.x * blockDim.x + threadIdx.x;
    if (i < NN) g_counts[i] = 1;   // self loop
}

__global__ void hist_kernel(const int* __restrict__ dst) {
    int e = blockIdx.x * blockDim.x + threadIdx.x;
    if (e < NE) atomicAdd(&g_counts[dst[e]], 1);
}

__global__ void scan1_kernel() {
    __shared__ int ss[256];
    int t = threadIdx.x, b = blockIdx.x;
    int base = b * 1024 + t * 4;
    int s = 0;
    #pragma unroll
    for (int q = 0; q < 4; q++) { int i = base + q; if (i < NN) s += g_counts[i]; }
    ss[t] = s;
    __syncthreads();
    for (int off = 1; off < 256; off <<= 1) {
        int v = (t >= off) ? ss[t - off] : 0;
        __syncthreads();
        ss[t] += v;
        __syncthreads();
    }
    if (t == 255) g_bsum[b] = ss[255];
}

__global__ void scan2_kernel() {
    __shared__ int ss[128];
    int t = threadIdx.x;
    ss[t] = (t < SBLK) ? g_bsum[t] : 0;
    __syncthreads();
    for (int off = 1; off < 128; off <<= 1) {
        int v = (t >= off) ? ss[t - off] : 0;
        __syncthreads();
        ss[t] += v;
        __syncthreads();
    }
    if (t < SBLK) g_boff[t] = t ? ss[t - 1] : 0;
    if (t == 127) g_rowptr[NN] = ss[127];
}

__global__ void scan3_kernel() {
    __shared__ int ss[256];
    int t = threadIdx.x, b = blockIdx.x;
    int base = b * 1024 + t * 4;
    int cnt[4]; int s = 0;
    #pragma unroll
    for (int q = 0; q < 4; q++) {
        cnt[q] = (base + q < NN) ? g_counts[base + q] : 0;
        s += cnt[q];
    }
    ss[t] = s;
    __syncthreads();
    for (int off = 1; off < 256; off <<= 1) {
        int v = (t >= off) ? ss[t - off] : 0;
        __syncthreads();
        ss[t] += v;
        __syncthreads();
    }
    int pre = g_boff[b] + (t ? ss[t - 1] : 0);
    #pragma unroll
    for (int q = 0; q < 4; q++) {
        int i = base + q;
        if (i < NN) { g_rowptr[i] = pre; g_cursor[i] = pre; pre += cnt[q]; }
    }
}

__global__ void csr_fill_kernel(const int* __restrict__ src, const int* __restrict__ dst) {
    int e = blockIdx.x * blockDim.x + threadIdx.x;
    if (e >= ETOT) return;
    int s, d;
    if (e < NE) { s = src[e]; d = dst[e]; } else { s = d = e - NE; }
    int pos = atomicAdd(&g_cursor[d], 1);
    g_col[pos] = s;
}

// ---------------- TF32 tensor-core GEMM ----------------
// C[M,N] = f(A)[M,K] @ B[K,N], row stride ldC; mode 0=id, 1=relu(A), 2=BN(A)
#define SAS 136

__device__ __forceinline__ uint32_t f2tf32(float f) {
    uint32_t u;
    asm("cvt.rna.tf32.f32 %0, %1;" : "=r"(u) : "f"(f));
    return u;
}

__global__ void gemm_tf32_kernel(const float* __restrict__ A,
                                 const float* __restrict__ Bl, const float* __restrict__ Br,
                                 float* __restrict__ Cl, float* __restrict__ Cr,
                                 int M, int N, int K, int ldC, int mode) {
    extern __shared__ uint32_t smem[];
    const int K4 = K + 4;
    uint32_t* sBT = smem;                 // [64][K4]
    uint32_t* sA  = smem + 64 * K4;       // [32][SAS]

    int tid = threadIdx.x;
    const float* Bg = blockIdx.z ? Br : Bl;
    float* Cg = blockIdx.z ? Cr : Cl;
    int col0 = blockIdx.x * 64;
    int row0 = blockIdx.y * 128;

    for (int i = tid; i < K * 16; i += 256) {
        int k = i >> 4, n4 = (i & 15) * 4;
        #pragma unroll
        for (int q = 0; q < 4; q++) {
            int n = n4 + q;
            float v = (col0 + n < N) ? Bg[(size_t)k * N + col0 + n] : 0.f;
            sBT[n * K4 + k] = f2tf32(v);
        }
    }

    int lane = tid & 31, w = tid >> 5;
    int mw = (w & 3) * 32, nw = (w >> 2) * 32;
    int g = lane >> 2, c = lane & 3;

    float acc[2][4][4] = {};

    for (int k0 = 0; k0 < K; k0 += 32) {
        #pragma unroll
        for (int l = 0; l < 4; l++) {
            int i = tid + l * 256;
            int r = i >> 3, c4 = (i & 7) * 4;
            int gr = row0 + r;
            float4 v = make_float4(0.f, 0.f, 0.f, 0.f);
            if (gr < M) v = *(const float4*)&A[(size_t)gr * K + k0 + c4];
            float vv[4] = {v.x, v.y, v.z, v.w};
            #pragma unroll
            for (int q = 0; q < 4; q++) {
                float f = vv[q];
                int kc = k0 + c4 + q;
                if (mode == 1) f = fmaxf(f, 0.f);
                else if (mode == 2) f = f * g_bnscale[kc] + g_bnshift[kc];
                sA[(c4 + q) * SAS + r] = f2tf32(f);
            }
        }
        __syncthreads();

        #pragma unroll
        for (int kk = 0; kk < 32; kk += 8) {
            uint32_t af[2][4], bf[4][2];
            #pragma unroll
            for (int mt = 0; mt < 2; mt++) {
                int mb = mw + mt * 16 + g;
                af[mt][0] = sA[(kk + c) * SAS + mb];
                af[mt][1] = sA[(kk + c) * SAS + mb + 8];
                af[mt][2] = sA[(kk + c + 4) * SAS + mb];
                af[mt][3] = sA[(kk + c + 4) * SAS + mb + 8];
            }
            #pragma unroll
            for (int nt = 0; nt < 4; nt++) {
                int nb = nw + nt * 8 + g;
                bf[nt][0] = sBT[nb * K4 + k0 + kk + c];
                bf[nt][1] = sBT[nb * K4 + k0 + kk + c + 4];
            }
            #pragma unroll
            for (int mt = 0; mt < 2; mt++)
                #pragma unroll
                for (int nt = 0; nt < 4; nt++) {
                    float* cc = acc[mt][nt];
                    asm volatile(
                        "mma.sync.aligned.m16n8k8.row.col.f32.tf32.tf32.f32 "
                        "{%0,%1,%2,%3}, {%4,%5,%6,%7}, {%8,%9}, {%0,%1,%2,%3};"
                        : "+f"(cc[0]), "+f"(cc[1]), "+f"(cc[2]), "+f"(cc[3])
                        : "r"(af[mt][0]), "r"(af[mt][1]), "r"(af[mt][2]), "r"(af[mt][3]),
                          "r"(bf[nt][0]), "r"(bf[nt][1]));
                }
        }
        __syncthreads();
    }

    #pragma unroll
    for (int mt = 0; mt < 2; mt++) {
        #pragma unroll
        for (int nt = 0; nt < 4; nt++) {
            int row = row0 + mw + mt * 16 + g;
            int col = col0 + nw + nt * 8 + 2 * c;
            float* cc = acc[mt][nt];
            if (row < M) {
                if (col < N)     Cg[(size_t)row * ldC + col]     = cc[0];
                if (col + 1 < N) Cg[(size_t)row * ldC + col + 1] = cc[1];
            }
            if (row + 8 < M) {
                if (col < N)     Cg[(size_t)(row + 8) * ldC + col]     = cc[2];
                if (col + 1 < N) Cg[(size_t)(row + 8) * ldC + col + 1] = cc[3];
            }
        }
    }
}

// ---------------- fused GAT layers (warp per node, float2, 2-edge unroll) ----------------
// lane covers dims {64j+2*lane, 64j+2*lane+1} for head j=0..2

__device__ __forceinline__ void gat_upd(float P, float& m, float& z, float2& a, float2 x) {
    if (P > m) {
        float sc = __expf(m - P);
        z = z * sc + 1.f;
        a.x = a.x * sc + x.x;
        a.y = a.y * sc + x.y;
        m = P;
    } else {
        float w = __expf(P - m);
        z += w;
        a.x += x.x * w;
        a.y += x.y * w;
    }
}

__device__ __forceinline__ void gat_core192(int n, int lane, const float* __restrict__ att,
                                            float2 (&acc)[3], float (&z)[3]) {
    const float2* prow = reinterpret_cast<const float2*>(g_xr + (size_t)n * HD192);
    const float2* patt = reinterpret_cast<const float2*>(att);
    float2 attr[3], xrr[3];
    float m[3];
    #pragma unroll
    for (int j = 0; j < 3; j++) {
        attr[j] = patt[32 * j + lane];
        xrr[j]  = prow[32 * j + lane];
        acc[j] = make_float2(0.f, 0.f);
        m[j] = -INFINITY; z[j] = 0.f;
    }
    int e  = g_rowptr[n];
    int e1 = g_rowptr[n + 1];

    for (; e + 2 <= e1; e += 2) {
        int s0 = g_col[e], s1 = g_col[e + 1];
        const float2* pa = reinterpret_cast<const float2*>(g_xl + (size_t)s0 * HD192);
        const float2* pb = reinterpret_cast<const float2*>(g_xl + (size_t)s1 * HD192);
        float2 xa[3], xb[3];
        #pragma unroll
        for (int j = 0; j < 3; j++) { xa[j] = pa[32 * j + lane]; xb[j] = pb[32 * j + lane]; }
        float p[3], q[3];
        #pragma unroll
        for (int j = 0; j < 3; j++) {
            float vx = xa[j].x + xrr[j].x; vx = (vx > 0.f) ? vx : 0.2f * vx;
            float vy = xa[j].y + xrr[j].y; vy = (vy > 0.f) ? vy : 0.2f * vy;
            p[j] = attr[j].x * vx + attr[j].y * vy;
            float wx = xb[j].x + xrr[j].x; wx = (wx > 0.f) ? wx : 0.2f * wx;
            float wy = xb[j].y + xrr[j].y; wy = (wy > 0.f) ? wy : 0.2f * wy;
            q[j] = attr[j].x * wx + attr[j].y * wy;
        }
        #pragma unroll
        for (int o = 16; o > 0; o >>= 1) {
            #pragma unroll
            for (int j = 0; j < 3; j++) {
                p[j] += __shfl_xor_sync(0xffffffffu, p[j], o);
                q[j] += __shfl_xor_sync(0xffffffffu, q[j], o);
            }
        }
        #pragma unroll
        for (int j = 0; j < 3; j++) {
            gat_upd(p[j], m[j], z[j], acc[j], xa[j]);
            gat_upd(q[j], m[j], z[j], acc[j], xb[j]);
        }
    }
    if (e < e1) {
        int s0 = g_col[e];
        const float2* pa = reinterpret_cast<const float2*>(g_xl + (size_t)s0 * HD192);
        float2 xa[3];
        #pragma unroll
        for (int j = 0; j < 3; j++) xa[j] = pa[32 * j + lane];
        float p[3];
        #pragma unroll
        for (int j = 0; j < 3; j++) {
            float vx = xa[j].x + xrr[j].x; vx = (vx > 0.f) ? vx : 0.2f * vx;
            float vy = xa[j].y + xrr[j].y; vy = (vy > 0.f) ? vy : 0.2f * vy;
            p[j] = attr[j].x * vx + attr[j].y * vy;
        }
        #pragma unroll
        for (int o = 16; o > 0; o >>= 1)
            #pragma unroll
            for (int j = 0; j < 3; j++)
                p[j] += __shfl_xor_sync(0xffffffffu, p[j], o);
        #pragma unroll
        for (int j = 0; j < 3; j++)
            gat_upd(p[j], m[j], z[j], acc[j], xa[j]);
    }
}

__global__ void gat1_kernel(const float* __restrict__ att, const float* __restrict__ b1) {
    __shared__ float sbn[HD192], sbq[HD192];
    int tid = threadIdx.x;
    if (tid < HD192) { sbn[tid] = 0.f; sbq[tid] = 0.f; }
    __syncthreads();
    int lane = tid & 31, wib = tid >> 5;
    int n = blockIdx.x * 8 + wib;
    if (n < NN) {
        float2 acc[3]; float z[3];
        gat_core192(n, lane, att, acc, z);
        float2* ph = reinterpret_cast<float2*>(g_h + (size_t)n * HD192);
        const float2* pb = reinterpret_cast<const float2*>(b1);
        #pragma unroll
        for (int j = 0; j < 3; j++) {
            float iz = 1.f / z[j];
            float2 b = pb[32 * j + lane];
            float ox = fmaxf(acc[j].x * iz + b.x, 0.f);
            float oy = fmaxf(acc[j].y * iz + b.y, 0.f);
            ph[32 * j + lane] = make_float2(ox, oy);
            int c = 64 * j + 2 * lane;
            atomicAdd(&sbn[c],     ox);
            atomicAdd(&sbn[c + 1], oy);
            atomicAdd(&sbq[c],     ox * ox);
            atomicAdd(&sbq[c + 1], oy * oy);
        }
    }
    __syncthreads();
    if (tid < HD192) {
        atomicAdd(&g_bnsum[tid], sbn[tid]);
        atomicAdd(&g_bnsq[tid], sbq[tid]);
    }
}

__global__ void bn_prep_kernel(const float* __restrict__ gamma, const float* __restrict__ beta) {
    int c = threadIdx.x;
    if (c < HD192) {
        float mu = g_bnsum[c] * (1.f / NN);
        float var = g_bnsq[c] * (1.f / NN) - mu * mu;
        float s = gamma[c] * rsqrtf(var + EPSBN);
        g_bnscale[c] = s;
        g_bnshift[c] = beta[c] - mu * s;
    }
}

__global__ void gat2_kernel(const float* __restrict__ att, const float* __restrict__ b2,
                            const int* __restrict__ batch) {
    int tid = threadIdx.x;
    int lane = tid & 31, wib = tid >> 5;
    int n = blockIdx.x * 8 + wib;
    if (n >= NN) return;
    float2 acc[3]; float z[3];
    gat_core192(n, lane, att, acc, z);
    float iz0 = 1.f / z[0], iz1 = 1.f / z[1], iz2 = 1.f / z[2];
    const float2* pb = reinterpret_cast<const float2*>(b2);
    float2 b = pb[lane];
    float2 v;
    v.x = (acc[0].x * iz0 + acc[1].x * iz1 + acc[2].x * iz2) * (1.f / 3.f) + b.x;
    v.y = (acc[0].y * iz0 + acc[1].y * iz1 + acc[2].y * iz2) * (1.f / 3.f) + b.y;
    reinterpret_cast<float2*>(g_h2 + (size_t)n * D64)[lane] = v;
    int bt = batch[n];
    atomicAdd(&g_pool[bt * D64 + 2 * lane],     v.x);
    atomicAdd(&g_pool[bt * D64 + 2 * lane + 1], v.y);
    if (lane == 0) atomicAdd(&g_cnt[bt], 1.f);
}

// layer 3: rows stored with stride 64 (col 63 is GEMM pad, masked to 0 here)
__global__ void gat3_kernel(const float* __restrict__ att, const float* __restrict__ b3,
                            float* __restrict__ out) {
    __shared__ float sh[8][64];
    int tid = threadIdx.x;
    int lane = tid & 31, wib = tid >> 5;
    int n = blockIdx.x * 8 + wib;
    if (n >= NN) return;
    int d0 = 2 * lane, d1 = d0 + 1;
    bool ok1 = (d1 < HD63);
    int h0 = d0 / D21;
    int h1 = ok1 ? (d1 / D21) : 2;
    float at0 = att[d0];
    float at1 = ok1 ? att[d1] : 0.f;
    float2 xr2 = reinterpret_cast<const float2*>(g_xr + (size_t)n * D64)[lane];
    if (!ok1) xr2.y = 0.f;
    float2 a = make_float2(0.f, 0.f);
    float m[3] = {-INFINITY, -INFINITY, -INFINITY};
    float z[3] = {0.f, 0.f, 0.f};
    int e  = g_rowptr[n];
    int e1 = g_rowptr[n + 1];
    for (; e + 2 <= e1; e += 2) {
        int s0 = g_col[e], s1 = g_col[e + 1];
        float2 xa = reinterpret_cast<const float2*>(g_xl + (size_t)s0 * D64)[lane];
        float2 xb = reinterpret_cast<const float2*>(g_xl + (size_t)s1 * D64)[lane];
        if (!ok1) { xa.y = 0.f; xb.y = 0.f; }
        float tax = xa.x + xr2.x; tax = (tax > 0.f) ? tax : 0.2f * tax;
        float tay = xa.y + xr2.y; tay = (tay > 0.f) ? tay : 0.2f * tay;
        float tbx = xb.x + xr2.x; tbx = (tbx > 0.f) ? tbx : 0.2f * tbx;
        float tby = xb.y + xr2.y; tby = (tby > 0.f) ? tby : 0.2f * tby;
        float qa0 = at0 * tax, qa1 = at1 * tay;
        float qb0 = at0 * tbx, qb1 = at1 * tby;
        float p[3], q[3];
        #pragma unroll
        for (int j = 0; j < 3; j++) {
            p[j] = ((h0 == j) ? qa0 : 0.f) + ((h1 == j && ok1) ? qa1 : 0.f);
            q[j] = ((h0 == j) ? qb0 : 0.f) + ((h1 == j && ok1) ? qb1 : 0.f);
        }
        #pragma unroll
        for (int o = 16; o > 0; o >>= 1) {
            #pragma unroll
            for (int j = 0; j < 3; j++) {
                p[j] += __shfl_xor_sync(0xffffffffu, p[j], o);
                q[j] += __shfl_xor_sync(0xffffffffu, q[j], o);
            }
        }
        float sc[3], wt[3];
        #pragma unroll
        for (int j = 0; j < 3; j++) {
            if (p[j] > m[j]) { sc[j] = __expf(m[j] - p[j]); wt[j] = 1.f; z[j] = z[j] * sc[j] + 1.f; m[j] = p[j]; }
            else             { sc[j] = 1.f; wt[j] = __expf(p[j] - m[j]); z[j] += wt[j]; }
        }
        a.x = a.x * sc[h0] + xa.x * wt[h0];
        a.y = a.y * sc[h1] + xa.y * wt[h1];
        #pragma unroll
        for (int j = 0; j < 3; j++) {
            if (q[j] > m[j]) { sc[j] = __expf(m[j] - q[j]); wt[j] = 1.f; z[j] = z[j] * sc[j] + 1.f; m[j] = q[j]; }
            else             { sc[j] = 1.f; wt[j] = __expf(q[j] - m[j]); z[j] += wt[j]; }
        }
        a.x = a.x * sc[h0] + xb.x * wt[h0];
        a.y = a.y * sc[h1] + xb.y * wt[h1];
    }
    if (e < e1) {
        int s0 = g_col[e];
        float2 xa = reinterpret_cast<const float2*>(g_xl + (size_t)s0 * D64)[lane];
        if (!ok1) xa.y = 0.f;
        float tax = xa.x + xr2.x; tax = (tax > 0.f) ? tax : 0.2f * tax;
        float tay = xa.y + xr2.y; tay = (tay > 0.f) ? tay : 0.2f * tay;
        float qa0 = at0 * tax, qa1 = at1 * tay;
        float p[3];
        #pragma unroll
        for (int j = 0; j < 3; j++)
            p[j] = ((h0 == j) ? qa0 : 0.f) + ((h1 == j && ok1) ? qa1 : 0.f);
        #pragma unroll
        for (int o = 16; o > 0; o >>= 1)
            #pragma unroll
            for (int j = 0; j < 3; j++)
                p[j] += __shfl_xor_sync(0xffffffffu, p[j], o);
        float sc[3], wt[3];
        #pragma unroll
        for (int j = 0; j < 3; j++) {
            if (p[j] > m[j]) { sc[j] = __expf(m[j] - p[j]); wt[j] = 1.f; z[j] = z[j] * sc[j] + 1.f; m[j] = p[j]; }
            else             { sc[j] = 1.f; wt[j] = __expf(p[j] - m[j]); z[j] += wt[j]; }
        }
        a.x = a.x * sc[h0] + xa.x * wt[h0];
        a.y = a.y * sc[h1] + xa.y * wt[h1];
    }
    sh[wib][d0] = a.x / z[h0];
    if (ok1) sh[wib][d1] = a.y / z[h1];
    __syncwarp();
    if (lane < D21) {
        float o = (sh[wib][lane] + sh[wib][lane + D21] + sh[wib][lane + 2 * D21]) * (1.f / 3.f)
                  + b3[lane];
        out[NG * NCLS + (size_t)n * D21 + lane] = o;
    }
}

__global__ void classifier_kernel(const float* __restrict__ Wc, const float* __restrict__ bc,
                                  float* __restrict__ out) {
    int t = threadIdx.x;
    if (t >= NG * NCLS) return;
    int g = t / NCLS, j = t % NCLS;
    float cnt = fmaxf(g_cnt[g], 1.f);
    float s = bc[j];
    #pragma unroll
    for (int d = 0; d < D64; d++)
        s += (g_pool[g * D64 + d] / cnt) * Wc[d * NCLS + j];
    out[t] = s;
}

// ---------------- launch (single stream, fully serial — round-6 structure) ----------------
extern "C" void kernel_launch(void* const* d_in, const int* in_sizes, int n_in,
                              void* d_out, int out_size) {
    const float* x     = (const float*)d_in[0];
    const int*   ei    = (const int*)d_in[1];
    const int*   batch = (const int*)d_in[2];
    const float* Wl1   = (const float*)d_in[3];
    const float* Wr1   = (const float*)d_in[4];
    const float* att1  = (const float*)d_in[5];
    const float* b1    = (const float*)d_in[6];
    const float* gamma = (const float*)d_in[7];
    const float* beta  = (const float*)d_in[8];
    const float* Wl2   = (const float*)d_in[9];
    const float* Wr2   = (const float*)d_in[10];
    const float* att2  = (const float*)d_in[11];
    const float* b2    = (const float*)d_in[12];
    const float* Wl3   = (const float*)d_in[13];
    const float* Wr3   = (const float*)d_in[14];
    const float* att3  = (const float*)d_in[15];
    const float* b3    = (const float*)d_in[16];
    const float* Wc    = (const float*)d_in[17];
    const float* bc    = (const float*)d_in[18];
    float* out = (float*)d_out;

    const int* src  = ei;
    const int* dstp = ei + NE;

    float *pxl, *pxr, *ph, *ph2;
    cudaGetSymbolAddress((void**)&pxl, g_xl);
    cudaGetSymbolAddress((void**)&pxr, g_xr);
    cudaGetSymbolAddress((void**)&ph,  g_h);
    cudaGetSymbolAddress((void**)&ph2, g_h2);

    auto smem_for = [](int K) { return (size_t)(64 * (K + 4) + 32 * SAS) * 4; };
    static bool attr_set = false;
    if (!attr_set) {
        cudaFuncSetAttribute(gemm_tf32_kernel,
                             cudaFuncAttributeMaxDynamicSharedMemorySize,
                             (int)smem_for(HD192));
        attr_set = true;
    }

    reset_small_kernel<<<1, 512>>>();

    // CSR build (reused by all three layers)
    init_counts_kernel<<<(NN + 255) / 256, 256>>>();
    hist_kernel<<<(NE + 255) / 256, 256>>>(dstp);
    scan1_kernel<<<SBLK, 256>>>();
    scan2_kernel<<<1, 128>>>();
    scan3_kernel<<<SBLK, 256>>>();
    csr_fill_kernel<<<(ETOT + 255) / 256, 256>>>(src, dstp);

    const int gat_grid = (NN + 7) / 8;
    const int my = (NN + 127) / 128;

    // ---- layer 1: x(128) -> 3x64 concat ----
    {
        dim3 g(3, my, 2);
        gemm_tf32_kernel<<<g, 256, smem_for(128)>>>(x, Wl1, Wr1, pxl, pxr, NN, HD192, 128, HD192, 0);
    }
    gat1_kernel<<<gat_grid, 256>>>(att1, b1);
    bn_prep_kernel<<<1, 256>>>(gamma, beta);

    // ---- layer 2: BN(h)(192) -> 64 (head mean), + pooling ----
    {
        dim3 g(3, my, 2);
        gemm_tf32_kernel<<<g, 256, smem_for(HD192)>>>(ph, Wl2, Wr2, pxl, pxr, NN, HD192, HD192, HD192, 2);
    }
    gat2_kernel<<<gat_grid, 256>>>(att2, b2, batch);
    classifier_kernel<<<1, 128>>>(Wc, bc, out);

    // ---- layer 3: relu(h2)(64) -> 21 (head mean), rows padded to stride 64 ----
    {
        dim3 g(1, my, 2);
        gemm_tf32_kernel<<<g, 256, smem_for(D64)>>>(ph2, Wl3, Wr3, pxl, pxr, NN, HD63, D64, D64, 1);
    }
    gat3_kernel<<<gat_grid, 256>>>(att3, b3, out);
}

// round 12
// speedup vs baseline: 1.3900x; 1.3900x over previous
#include <cuda_runtime.h>
#include <math.h>
#include <stdint.h>

#define NN 100000
#define NE 1600000
#define ETOT (NE + NN)
#define HD192 192
#define D64 64
#define HD63 63
#define D21 21
#define NG 8
#define NCLS 10
#define EPSBN 1e-5f
#define SBLK 98          // scan blocks: 98 * 1024 >= NN

// ---------------- scratch (device globals; no allocs allowed) ----------------
__device__ float g_xl[(size_t)NN * HD192];
__device__ float g_xr[(size_t)NN * HD192];
__device__ float g_h[(size_t)NN * HD192];
__device__ float g_h2[(size_t)NN * D64];
__device__ int   g_counts[NN];
__device__ int   g_rowptr[NN + 1];
__device__ int   g_cursor[NN];
__device__ int   g_col[ETOT];
__device__ int   g_bsum[SBLK];
__device__ int   g_boff[SBLK];
__device__ float g_bnsum[HD192];
__device__ float g_bnsq[HD192];
__device__ float g_bnscale[HD192];
__device__ float g_bnshift[HD192];
__device__ float g_pool[NG * D64];
__device__ float g_cnt[NG];

// ---------------- small resets ----------------
__global__ void reset_small_kernel() {
    int t = threadIdx.x;
    if (t < HD192) { g_bnsum[t] = 0.f; g_bnsq[t] = 0.f; }
    if (t < NG * D64) g_pool[t] = 0.f;
    if (t < NG) g_cnt[t] = 0.f;
}

// ---------------- CSR build ----------------
__global__ void init_counts_kernel() {
    int i = blockIdx.x * blockDim.x + threadIdx.x;
    if (i < NN) g_counts[i] = 1;   // self loop
}

__global__ void hist_kernel(const int* __restrict__ dst) {
    int e = blockIdx.x * blockDim.x + threadIdx.x;
    if (e < NE) atomicAdd(&g_counts[dst[e]], 1);
}

__global__ void scan1_kernel() {
    __shared__ int ss[256];
    int t = threadIdx.x, b = blockIdx.x;
    int base = b * 1024 + t * 4;
    int s = 0;
    #pragma unroll
    for (int q = 0; q < 4; q++) { int i = base + q; if (i < NN) s += g_counts[i]; }
    ss[t] = s;
    __syncthreads();
    for (int off = 1; off < 256; off <<= 1) {
        int v = (t >= off) ? ss[t - off] : 0;
        __syncthreads();
        ss[t] += v;
        __syncthreads();
    }
    if (t == 255) g_bsum[b] = ss[255];
}

__global__ void scan2_kernel() {
    __shared__ int ss[128];
    int t = threadIdx.x;
    ss[t] = (t < SBLK) ? g_bsum[t] : 0;
    __syncthreads();
    for (int off = 1; off < 128; off <<= 1) {
        int v = (t >= off) ? ss[t - off] : 0;
        __syncthreads();
        ss[t] += v;
        __syncthreads();
    }
    if (t < SBLK) g_boff[t] = t ? ss[t - 1] : 0;
    if (t == 127) g_rowptr[NN] = ss[127];
}

__global__ void scan3_kernel() {
    __shared__ int ss[256];
    int t = threadIdx.x, b = blockIdx.x;
    int base = b * 1024 + t * 4;
    int cnt[4]; int s = 0;
    #pragma unroll
    for (int q = 0; q < 4; q++) {
        cnt[q] = (base + q < NN) ? g_counts[base + q] : 0;
        s += cnt[q];
    }
    ss[t] = s;
    __syncthreads();
    for (int off = 1; off < 256; off <<= 1) {
        int v = (t >= off) ? ss[t - off] : 0;
        __syncthreads();
        ss[t] += v;
        __syncthreads();
    }
    int pre = g_boff[b] + (t ? ss[t - 1] : 0);
    #pragma unroll
    for (int q = 0; q < 4; q++) {
        int i = base + q;
        if (i < NN) { g_rowptr[i] = pre; g_cursor[i] = pre; pre += cnt[q]; }
    }
}

__global__ void csr_fill_kernel(const int* __restrict__ src, const int* __restrict__ dst) {
    int e = blockIdx.x * blockDim.x + threadIdx.x;
    if (e >= ETOT) return;
    int s, d;
    if (e < NE) { s = src[e]; d = dst[e]; } else { s = d = e - NE; }
    int pos = atomicAdd(&g_cursor[d], 1);
    g_col[pos] = s;
}

// ---------------- TF32 tensor-core GEMM ----------------
// C[M,N] = f(A)[M,K] @ B[K,N], row stride ldC; mode 0=id, 1=relu(A), 2=BN(A)
#define SAS 136

__device__ __forceinline__ uint32_t f2tf32(float f) {
    uint32_t u;
    asm("cvt.rna.tf32.f32 %0, %1;" : "=r"(u) : "f"(f));
    return u;
}

__global__ void gemm_tf32_kernel(const float* __restrict__ A,
                                 const float* __restrict__ Bl, const float* __restrict__ Br,
                                 float* __restrict__ Cl, float* __restrict__ Cr,
                                 int M, int N, int K, int ldC, int mode) {
    extern __shared__ uint32_t smem[];
    const int K4 = K + 4;
    uint32_t* sBT = smem;                 // [64][K4]
    uint32_t* sA  = smem + 64 * K4;       // [32][SAS]

    int tid = threadIdx.x;
    const float* Bg = blockIdx.z ? Br : Bl;
    float* Cg = blockIdx.z ? Cr : Cl;
    int col0 = blockIdx.x * 64;
    int row0 = blockIdx.y * 128;

    for (int i = tid; i < K * 16; i += 256) {
        int k = i >> 4, n4 = (i & 15) * 4;
        #pragma unroll
        for (int q = 0; q < 4; q++) {
            int n = n4 + q;
            float v = (col0 + n < N) ? Bg[(size_t)k * N + col0 + n] : 0.f;
            sBT[n * K4 + k] = f2tf32(v);
        }
    }

    int lane = tid & 31, w = tid >> 5;
    int mw = (w & 3) * 32, nw = (w >> 2) * 32;
    int g = lane >> 2, c = lane & 3;

    float acc[2][4][4] = {};

    for (int k0 = 0; k0 < K; k0 += 32) {
        #pragma unroll
        for (int l = 0; l < 4; l++) {
            int i = tid + l * 256;
            int r = i >> 3, c4 = (i & 7) * 4;
            int gr = row0 + r;
            float4 v = make_float4(0.f, 0.f, 0.f, 0.f);
            if (gr < M) v = *(const float4*)&A[(size_t)gr * K + k0 + c4];
            float vv[4] = {v.x, v.y, v.z, v.w};
            #pragma unroll
            for (int q = 0; q < 4; q++) {
                float f = vv[q];
                int kc = k0 + c4 + q;
                if (mode == 1) f = fmaxf(f, 0.f);
                else if (mode == 2) f = f * g_bnscale[kc] + g_bnshift[kc];
                sA[(c4 + q) * SAS + r] = f2tf32(f);
            }
        }
        __syncthreads();

        #pragma unroll
        for (int kk = 0; kk < 32; kk += 8) {
            uint32_t af[2][4], bf[4][2];
            #pragma unroll
            for (int mt = 0; mt < 2; mt++) {
                int mb = mw + mt * 16 + g;
                af[mt][0] = sA[(kk + c) * SAS + mb];
                af[mt][1] = sA[(kk + c) * SAS + mb + 8];
                af[mt][2] = sA[(kk + c + 4) * SAS + mb];
                af[mt][3] = sA[(kk + c + 4) * SAS + mb + 8];
            }
            #pragma unroll
            for (int nt = 0; nt < 4; nt++) {
                int nb = nw + nt * 8 + g;
                bf[nt][0] = sBT[nb * K4 + k0 + kk + c];
                bf[nt][1] = sBT[nb * K4 + k0 + kk + c + 4];
            }
            #pragma unroll
            for (int mt = 0; mt < 2; mt++)
                #pragma unroll
                for (int nt = 0; nt < 4; nt++) {
                    float* cc = acc[mt][nt];
                    asm volatile(
                        "mma.sync.aligned.m16n8k8.row.col.f32.tf32.tf32.f32 "
                        "{%0,%1,%2,%3}, {%4,%5,%6,%7}, {%8,%9}, {%0,%1,%2,%3};"
                        : "+f"(cc[0]), "+f"(cc[1]), "+f"(cc[2]), "+f"(cc[3])
                        : "r"(af[mt][0]), "r"(af[mt][1]), "r"(af[mt][2]), "r"(af[mt][3]),
                          "r"(bf[nt][0]), "r"(bf[nt][1]));
                }
        }
        __syncthreads();
    }

    #pragma unroll
    for (int mt = 0; mt < 2; mt++) {
        #pragma unroll
        for (int nt = 0; nt < 4; nt++) {
            int row = row0 + mw + mt * 16 + g;
            int col = col0 + nw + nt * 8 + 2 * c;
            float* cc = acc[mt][nt];
            if (row < M) {
                if (col < N)     Cg[(size_t)row * ldC + col]     = cc[0];
                if (col + 1 < N) Cg[(size_t)row * ldC + col + 1] = cc[1];
            }
            if (row + 8 < M) {
                if (col < N)     Cg[(size_t)(row + 8) * ldC + col]     = cc[2];
                if (col + 1 < N) Cg[(size_t)(row + 8) * ldC + col + 1] = cc[3];
            }
        }
    }
}

// ---------------- fused GAT layers (warp per node, scalar round-6 core + prefetch) ----------------
#define ONLINE_UPDATE(P, M, Z, A0, A1, X0, X1)                          \
    if (P > M) {                                                         \
        float sc_ = __expf(M - P); Z = Z * sc_ + 1.f;                    \
        A0 = A0 * sc_ + X0; A1 = A1 * sc_ + X1; M = P;                   \
    } else {                                                             \
        float w_ = __expf(P - M); Z += w_;                               \
        A0 += X0 * w_; A1 += X1 * w_;                                    \
    }

// acc/z laid out as round 6: element c = lane + 32*i (i=0..5), head = i/2
__device__ __forceinline__ void gat_core192(int n, int lane, const float* __restrict__ att,
                                            float (&acc)[6], float (&z)[3]) {
    const float* pr = g_xr + (size_t)n * HD192;
    float attr[6], xrr[6];
    #pragma unroll
    for (int i = 0; i < 6; i++) {
        int c = lane + 32 * i;
        attr[i] = att[c]; xrr[i] = pr[c]; acc[i] = 0.f;
    }
    float m0 = -INFINITY, m1 = -INFINITY, m2 = -INFINITY;
    float z0 = 0.f, z1 = 0.f, z2 = 0.f;
    int e  = g_rowptr[n];
    int e1 = g_rowptr[n + 1];

    // prefetch first edge (deg >= 1 guaranteed by self loop)
    float xn[6];
    {
        int s = __ldg(&g_col[e]);
        const float* px = g_xl + (size_t)s * HD192;
        #pragma unroll
        for (int i = 0; i < 6; i++) xn[i] = px[lane + 32 * i];
    }
    for (; e < e1; e++) {
        float xv[6];
        #pragma unroll
        for (int i = 0; i < 6; i++) xv[i] = xn[i];
        if (e + 1 < e1) {
            int s = __ldg(&g_col[e + 1]);
            const float* px = g_xl + (size_t)s * HD192;
            #pragma unroll
            for (int i = 0; i < 6; i++) xn[i] = px[lane + 32 * i];
        }
        float p0 = 0.f, p1 = 0.f, p2 = 0.f;
        #pragma unroll
        for (int i = 0; i < 6; i++) {
            float v = xv[i] + xrr[i];
            v = (v > 0.f) ? v : 0.2f * v;
            float pv = attr[i] * v;
            if (i < 2) p0 += pv; else if (i < 4) p1 += pv; else p2 += pv;
        }
        #pragma unroll
        for (int o = 16; o > 0; o >>= 1) {
            p0 += __shfl_xor_sync(0xffffffffu, p0, o);
            p1 += __shfl_xor_sync(0xffffffffu, p1, o);
            p2 += __shfl_xor_sync(0xffffffffu, p2, o);
        }
        ONLINE_UPDATE(p0, m0, z0, acc[0], acc[1], xv[0], xv[1])
        ONLINE_UPDATE(p1, m1, z1, acc[2], acc[3], xv[2], xv[3])
        ONLINE_UPDATE(p2, m2, z2, acc[4], acc[5], xv[4], xv[5])
    }
    z[0] = z0; z[1] = z1; z[2] = z2;
}

__global__ void gat1_kernel(const float* __restrict__ att, const float* __restrict__ b1) {
    __shared__ float sbn[HD192], sbq[HD192];
    int tid = threadIdx.x;
    if (tid < HD192) { sbn[tid] = 0.f; sbq[tid] = 0.f; }
    __syncthreads();
    int lane = tid & 31, wib = tid >> 5;
    int n = blockIdx.x * 8 + wib;
    if (n < NN) {
        float acc[6]; float z[3];
        gat_core192(n, lane, att, acc, z);
        float iz[3] = {1.f / z[0], 1.f / z[1], 1.f / z[2]};
        float* ph = g_h + (size_t)n * HD192;
        #pragma unroll
        for (int i = 0; i < 6; i++) {
            int c = lane + 32 * i;
            float o = acc[i] * iz[i >> 1] + b1[c];
            o = fmaxf(o, 0.f);
            ph[c] = o;
            atomicAdd(&sbn[c], o);
            atomicAdd(&sbq[c], o * o);
        }
    }
    __syncthreads();
    if (tid < HD192) {
        atomicAdd(&g_bnsum[tid], sbn[tid]);
        atomicAdd(&g_bnsq[tid], sbq[tid]);
    }
}

__global__ void bn_prep_kernel(const float* __restrict__ gamma, const float* __restrict__ beta) {
    int c = threadIdx.x;
    if (c < HD192) {
        float mu = g_bnsum[c] * (1.f / NN);
        float var = g_bnsq[c] * (1.f / NN) - mu * mu;
        float s = gamma[c] * rsqrtf(var + EPSBN);
        g_bnscale[c] = s;
        g_bnshift[c] = beta[c] - mu * s;
    }
}

__global__ void gat2_kernel(const float* __restrict__ att, const float* __restrict__ b2,
                            const int* __restrict__ batch) {
    int tid = threadIdx.x;
    int lane = tid & 31, wib = tid >> 5;
    int n = blockIdx.x * 8 + wib;
    if (n >= NN) return;
    float acc[6]; float z[3];
    gat_core192(n, lane, att, acc, z);
    float iz0 = 1.f / z[0], iz1 = 1.f / z[1], iz2 = 1.f / z[2];
    // element c = lane + 32i -> out dim d = c % 64; acc[0,2,4] -> d=lane; acc[1,3,5] -> d=lane+32
    float v0 = (acc[0] * iz0 + acc[2] * iz1 + acc[4] * iz2) * (1.f / 3.f) + b2[lane];
    float v1 = (acc[1] * iz0 + acc[3] * iz1 + acc[5] * iz2) * (1.f / 3.f) + b2[lane + 32];
    float* ph2 = g_h2 + (size_t)n * D64;
    ph2[lane] = v0;
    ph2[lane + 32] = v1;
    int b = batch[n];
    atomicAdd(&g_pool[b * D64 + lane], v0);
    atomicAdd(&g_pool[b * D64 + lane + 32], v1);
    if (lane == 0) atomicAdd(&g_cnt[b], 1.f);
}

// layer 3: round-6 scalar version (rows stride HD63) + prefetch
__global__ void gat3_kernel(const float* __restrict__ att, const float* __restrict__ b3,
                            float* __restrict__ out) {
    __shared__ float sh[8][64];
    int tid = threadIdx.x;
    int lane = tid & 31, wib = tid >> 5;
    int n = blockIdx.x * 8 + wib;
    if (n >= NN) return;
    int c0 = lane, c1 = lane + 32;
    int h0 = c0 / D21;                     // 0 or 1
    int h1 = c1 / D21;                     // 1 or 2 (c1 < 63)
    bool v1ok = (c1 < HD63);
    float attr0 = att[c0], attr1 = v1ok ? att[c1] : 0.f;
    const float* pr = g_xr + (size_t)n * HD63;
    float xr0 = pr[c0], xr1 = v1ok ? pr[c1] : 0.f;
    float a0 = 0.f, a1 = 0.f;
    float m0 = -INFINITY, m1 = -INFINITY, m2 = -INFINITY;
    float z0 = 0.f, z1 = 0.f, z2 = 0.f;
    int e  = g_rowptr[n];
    int e1 = g_rowptr[n + 1];

    float xn0, xn1;
    {
        int s = __ldg(&g_col[e]);
        const float* px = g_xl + (size_t)s * HD63;
        xn0 = px[c0];
        xn1 = v1ok ? px[c1] : 0.f;
    }
    for (; e < e1; e++) {
        float x0 = xn0, x1 = xn1;
        if (e + 1 < e1) {
            int s = __ldg(&g_col[e + 1]);
            const float* px = g_xl + (size_t)s * HD63;
            xn0 = px[c0];
            xn1 = v1ok ? px[c1] : 0.f;
        }
        float t0 = x0 + xr0; t0 = (t0 > 0.f) ? t0 : 0.2f * t0;
        float t1 = x1 + xr1; t1 = (t1 > 0.f) ? t1 : 0.2f * t1;
        float q0 = attr0 * t0, q1 = attr1 * t1;
        float p0 = (h0 == 0) ? q0 : 0.f;
        float p1 = ((h0 == 1) ? q0 : 0.f) + ((h1 == 1) ? q1 : 0.f);
        float p2 = (h1 == 2) ? q1 : 0.f;
        #pragma unroll
        for (int o = 16; o > 0; o >>= 1) {
            p0 += __shfl_xor_sync(0xffffffffu, p0, o);
            p1 += __shfl_xor_sync(0xffffffffu, p1, o);
            p2 += __shfl_xor_sync(0xffffffffu, p2, o);
        }
        float sc0, wt0, sc1, wt1, sc2, wt2;
        if (p0 > m0) { sc0 = __expf(m0 - p0); wt0 = 1.f; z0 = z0 * sc0 + 1.f; m0 = p0; }
        else         { sc0 = 1.f; wt0 = __expf(p0 - m0); z0 += wt0; }
        if (p1 > m1) { sc1 = __expf(m1 - p1); wt1 = 1.f; z1 = z1 * sc1 + 1.f; m1 = p1; }
        else         { sc1 = 1.f; wt1 = __expf(p1 - m1); z1 += wt1; }
        if (p2 > m2) { sc2 = __expf(m2 - p2); wt2 = 1.f; z2 = z2 * sc2 + 1.f; m2 = p2; }
        else         { sc2 = 1.f; wt2 = __expf(p2 - m2); z2 += wt2; }
        float sA0 = (h0 == 0) ? sc0 : sc1, wA0 = (h0 == 0) ? wt0 : wt1;
        float sA1 = (h1 == 1) ? sc1 : sc2, wA1 = (h1 == 1) ? wt1 : wt2;
        a0 = a0 * sA0 + x0 * wA0;
        a1 = a1 * sA1 + x1 * wA1;
    }
    float iz0 = 1.f / z0, iz1 = 1.f / z1, iz2 = 1.f / z2;
    sh[wib][c0] = a0 * ((h0 == 0) ? iz0 : iz1);
    if (v1ok) sh[wib][c1] = a1 * ((h1 == 1) ? iz1 : iz2);
    __syncwarp();
    if (lane < D21) {
        float o = (sh[wib][lane] + sh[wib][lane + D21] + sh[wib][lane + 2 * D21]) * (1.f / 3.f)
                  + b3[lane];
        out[NG * NCLS + (size_t)n * D21 + lane] = o;
    }
}

__global__ void classifier_kernel(const float* __restrict__ Wc, const float* __restrict__ bc,
                                  float* __restrict__ out) {
    int t = threadIdx.x;
    if (t >= NG * NCLS) return;
    int g = t / NCLS, j = t % NCLS;
    float cnt = fmaxf(g_cnt[g], 1.f);
    float s = bc[j];
    #pragma unroll
    for (int d = 0; d < D64; d++)
        s += (g_pool[g * D64 + d] / cnt) * Wc[d * NCLS + j];
    out[t] = s;
}

// ---------------- launch (single stream, fully serial — round-6 structure) ----------------
extern "C" void kernel_launch(void* const* d_in, const int* in_sizes, int n_in,
                              void* d_out, int out_size) {
    const float* x     = (const float*)d_in[0];
    const int*   ei    = (const int*)d_in[1];
    const int*   batch = (const int*)d_in[2];
    const float* Wl1   = (const float*)d_in[3];
    const float* Wr1   = (const float*)d_in[4];
    const float* att1  = (const float*)d_in[5];
    const float* b1    = (const float*)d_in[6];
    const float* gamma = (const float*)d_in[7];
    const float* beta  = (const float*)d_in[8];
    const float* Wl2   = (const float*)d_in[9];
    const float* Wr2   = (const float*)d_in[10];
    const float* att2  = (const float*)d_in[11];
    const float* b2    = (const float*)d_in[12];
    const float* Wl3   = (const float*)d_in[13];
    const float* Wr3   = (const float*)d_in[14];
    const float* att3  = (const float*)d_in[15];
    const float* b3    = (const float*)d_in[16];
    const float* Wc    = (const float*)d_in[17];
    const float* bc    = (const float*)d_in[18];
    float* out = (float*)d_out;

    const int* src  = ei;
    const int* dstp = ei + NE;

    float *pxl, *pxr, *ph, *ph2;
    cudaGetSymbolAddress((void**)&pxl, g_xl);
    cudaGetSymbolAddress((void**)&pxr, g_xr);
    cudaGetSymbolAddress((void**)&ph,  g_h);
    cudaGetSymbolAddress((void**)&ph2, g_h2);

    auto smem_for = [](int K) { return (size_t)(64 * (K + 4) + 32 * SAS) * 4; };
    static bool attr_set = false;
    if (!attr_set) {
        cudaFuncSetAttribute(gemm_tf32_kernel,
                             cudaFuncAttributeMaxDynamicSharedMemorySize,
                             (int)smem_for(HD192));
        attr_set = true;
    }

    reset_small_kernel<<<1, 512>>>();

    // CSR build (reused by all three layers)
    init_counts_kernel<<<(NN + 255) / 256, 256>>>();
    hist_kernel<<<(NE + 255) / 256, 256>>>(dstp);
    scan1_kernel<<<SBLK, 256>>>();
    scan2_kernel<<<1, 128>>>();
    scan3_kernel<<<SBLK, 256>>>();
    csr_fill_kernel<<<(ETOT + 255) / 256, 256>>>(src, dstp);

    const int gat_grid = (NN + 7) / 8;
    const int my = (NN + 127) / 128;

    // ---- layer 1: x(128) -> 3x64 concat ----
    {
        dim3 g(3, my, 2);
        gemm_tf32_kernel<<<g, 256, smem_for(128)>>>(x, Wl1, Wr1, pxl, pxr, NN, HD192, 128, HD192, 0);
    }
    gat1_kernel<<<gat_grid, 256>>>(att1, b1);
    bn_prep_kernel<<<1, 256>>>(gamma, beta);

    // ---- layer 2: BN(h)(192) -> 64 (head mean), + pooling ----
    {
        dim3 g(3, my, 2);
        gemm_tf32_kernel<<<g, 256, smem_for(HD192)>>>(ph, Wl2, Wr2, pxl, pxr, NN, HD192, HD192, HD192, 2);
    }
    gat2_kernel<<<gat_grid, 256>>>(att2, b2, batch);
    classifier_kernel<<<1, 128>>>(Wc, bc, out);

    // ---- layer 3: relu(h2)(64) -> 21 (head mean), rows stride HD63 (round-6 layout) ----
    {
        dim3 g(1, my, 2);
        gemm_tf32_kernel<<<g, 256, smem_for(D64)>>>(ph2, Wl3, Wr3, pxl, pxr, NN, HD63, D64, HD63, 1);
    }
    gat3_kernel<<<gat_grid, 256>>>(att3, b3, out);
}

// round 15
// speedup vs baseline: 1.5330x; 1.1029x over previous
#include <cuda_runtime.h>
#include <math.h>
#include <stdint.h>

#define NN 100000
#define NE 1600000
#define ETOT (NE + NN)
#define HD192 192
#define D64 64
#define HD63 63
#define D21 21
#define NG 8
#define NCLS 10
#define EPSBN 1e-5f
#define SBLK 98          // scan blocks: 98 * 1024 >= NN

// ---------------- scratch (device globals; no allocs allowed) ----------------
__device__ float g_xl[(size_t)NN * HD192];
__device__ float g_xr[(size_t)NN * HD192];
__device__ float g_h[(size_t)NN * HD192];
__device__ float g_h2[(size_t)NN * D64];
__device__ int   g_counts[NN];
__device__ int   g_rowptr[NN + 1];
__device__ int   g_cursor[NN];
__device__ int   g_col[ETOT];
__device__ int   g_bsum[SBLK];
__device__ int   g_boff[SBLK];
__device__ float g_bnsum[HD192];
__device__ float g_bnsq[HD192];
__device__ float g_bnscale[HD192];
__device__ float g_bnshift[HD192];
__device__ float g_pool[NG * D64];
__device__ float g_cnt[NG];

// ---------------- small resets ----------------
__global__ void reset_small_kernel() {
    int t = threadIdx.x;
    if (t < HD192) { g_bnsum[t] = 0.f; g_bnsq[t] = 0.f; }
    if (t < NG * D64) g_pool[t] = 0.f;
    if (t < NG) g_cnt[t] = 0.f;
}

// ---------------- CSR build ----------------
__global__ void init_counts_kernel() {
    int i = blockIdx.x * blockDim.x + threadIdx.x;
    if (i < NN) g_counts[i] = 1;   // self loop
}

__global__ void hist_kernel(const int* __restrict__ dst) {
    int e = blockIdx.x * blockDim.x + threadIdx.x;
    if (e < NE) atomicAdd(&g_counts[dst[e]], 1);
}

__global__ void scan1_kernel() {
    __shared__ int ss[256];
    int t = threadIdx.x, b = blockIdx.x;
    int base = b * 1024 + t * 4;
    int s = 0;
    #pragma unroll
    for (int q = 0; q < 4; q++) { int i = base + q; if (i < NN) s += g_counts[i]; }
    ss[t] = s;
    __syncthreads();
    for (int off = 1; off < 256; off <<= 1) {
        int v = (t >= off) ? ss[t - off] : 0;
        __syncthreads();
        ss[t] += v;
        __syncthreads();
    }
    if (t == 255) g_bsum[b] = ss[255];
}

__global__ void scan2_kernel() {
    __shared__ int ss[128];
    int t = threadIdx.x;
    ss[t] = (t < SBLK) ? g_bsum[t] : 0;
    __syncthreads();
    for (int off = 1; off < 128; off <<= 1) {
        int v = (t >= off) ? ss[t - off] : 0;
        __syncthreads();
        ss[t] += v;
        __syncthreads();
    }
    if (t < SBLK) g_boff[t] = t ? ss[t - 1] : 0;
    if (t == 127) g_rowptr[NN] = ss[127];
}

__global__ void scan3_kernel() {
    __shared__ int ss[256];
    int t = threadIdx.x, b = blockIdx.x;
    int base = b * 1024 + t * 4;
    int cnt[4]; int s = 0;
    #pragma unroll
    for (int q = 0; q < 4; q++) {
        cnt[q] = (base + q < NN) ? g_counts[base + q] : 0;
        s += cnt[q];
    }
    ss[t] = s;
    __syncthreads();
    for (int off = 1; off < 256; off <<= 1) {
        int v = (t >= off) ? ss[t - off] : 0;
        __syncthreads();
        ss[t] += v;
        __syncthreads();
    }
    int pre = g_boff[b] + (t ? ss[t - 1] : 0);
    #pragma unroll
    for (int q = 0; q < 4; q++) {
        int i = base + q;
        if (i < NN) { g_rowptr[i] = pre; g_cursor[i] = pre; pre += cnt[q]; }
    }
}

__global__ void csr_fill_kernel(const int* __restrict__ src, const int* __restrict__ dst) {
    int e = blockIdx.x * blockDim.x + threadIdx.x;
    if (e >= ETOT) return;
    int s, d;
    if (e < NE) { s = src[e]; d = dst[e]; } else { s = d = e - NE; }
    int pos = atomicAdd(&g_cursor[d], 1);
    g_col[pos] = s;
}

// ---------------- TF32 tensor-core GEMM ----------------
// C[M,N] = f(A)[M,K] @ B[K,N], row stride ldC; mode 0=id, 1=relu(A), 2=BN(A)
#define SAS 136

__device__ __forceinline__ uint32_t f2tf32(float f) {
    uint32_t u;
    asm("cvt.rna.tf32.f32 %0, %1;" : "=r"(u) : "f"(f));
    return u;
}

__global__ void gemm_tf32_kernel(const float* __restrict__ A,
                                 const float* __restrict__ Bl, const float* __restrict__ Br,
                                 float* __restrict__ Cl, float* __restrict__ Cr,
                                 int M, int N, int K, int ldC, int mode) {
    extern __shared__ uint32_t smem[];
    const int K4 = K + 4;
    uint32_t* sBT = smem;                 // [64][K4]
    uint32_t* sA  = smem + 64 * K4;       // [32][SAS]

    int tid = threadIdx.x;
    const float* Bg = blockIdx.z ? Br : Bl;
    float* Cg = blockIdx.z ? Cr : Cl;
    int col0 = blockIdx.x * 64;
    int row0 = blockIdx.y * 128;

    for (int i = tid; i < K * 16; i += 256) {
        int k = i >> 4, n4 = (i & 15) * 4;
        #pragma unroll
        for (int q = 0; q < 4; q++) {
            int n = n4 + q;
            float v = (col0 + n < N) ? Bg[(size_t)k * N + col0 + n] : 0.f;
            sBT[n * K4 + k] = f2tf32(v);
        }
    }

    int lane = tid & 31, w = tid >> 5;
    int mw = (w & 3) * 32, nw = (w >> 2) * 32;
    int g = lane >> 2, c = lane & 3;

    float acc[2][4][4] = {};

    for (int k0 = 0; k0 < K; k0 += 32) {
        #pragma unroll
        for (int l = 0; l < 4; l++) {
            int i = tid + l * 256;
            int r = i >> 3, c4 = (i & 7) * 4;
            int gr = row0 + r;
            float4 v = make_float4(0.f, 0.f, 0.f, 0.f);
            if (gr < M) v = *(const float4*)&A[(size_t)gr * K + k0 + c4];
            float vv[4] = {v.x, v.y, v.z, v.w};
            #pragma unroll
            for (int q = 0; q < 4; q++) {
                float f = vv[q];
                int kc = k0 + c4 + q;
                if (mode == 1) f = fmaxf(f, 0.f);
                else if (mode == 2) f = f * g_bnscale[kc] + g_bnshift[kc];
                sA[(c4 + q) * SAS + r] = f2tf32(f);
            }
        }
        __syncthreads();

        #pragma unroll
        for (int kk = 0; kk < 32; kk += 8) {
            uint32_t af[2][4], bf[4][2];
            #pragma unroll
            for (int mt = 0; mt < 2; mt++) {
                int mb = mw + mt * 16 + g;
                af[mt][0] = sA[(kk + c) * SAS + mb];
                af[mt][1] = sA[(kk + c) * SAS + mb + 8];
                af[mt][2] = sA[(kk + c + 4) * SAS + mb];
                af[mt][3] = sA[(kk + c + 4) * SAS + mb + 8];
            }
            #pragma unroll
            for (int nt = 0; nt < 4; nt++) {
                int nb = nw + nt * 8 + g;
                bf[nt][0] = sBT[nb * K4 + k0 + kk + c];
                bf[nt][1] = sBT[nb * K4 + k0 + kk + c + 4];
            }
            #pragma unroll
            for (int mt = 0; mt < 2; mt++)
                #pragma unroll
                for (int nt = 0; nt < 4; nt++) {
                    float* cc = acc[mt][nt];
                    asm volatile(
                        "mma.sync.aligned.m16n8k8.row.col.f32.tf32.tf32.f32 "
                        "{%0,%1,%2,%3}, {%4,%5,%6,%7}, {%8,%9}, {%0,%1,%2,%3};"
                        : "+f"(cc[0]), "+f"(cc[1]), "+f"(cc[2]), "+f"(cc[3])
                        : "r"(af[mt][0]), "r"(af[mt][1]), "r"(af[mt][2]), "r"(af[mt][3]),
                          "r"(bf[nt][0]), "r"(bf[nt][1]));
                }
        }
        __syncthreads();
    }

    #pragma unroll
    for (int mt = 0; mt < 2; mt++) {
        #pragma unroll
        for (int nt = 0; nt < 4; nt++) {
            int row = row0 + mw + mt * 16 + g;
            int col = col0 + nw + nt * 8 + 2 * c;
            float* cc = acc[mt][nt];
            if (row < M) {
                if (col < N)     Cg[(size_t)row * ldC + col]     = cc[0];
                if (col + 1 < N) Cg[(size_t)row * ldC + col + 1] = cc[1];
            }
            if (row + 8 < M) {
                if (col < N)     Cg[(size_t)(row + 8) * ldC + col]     = cc[2];
                if (col + 1 < N) Cg[(size_t)(row + 8) * ldC + col + 1] = cc[3];
            }
        }
    }
}

// ---------------- warp reduction: shuffle butterfly (sm_103 has no redux.f32) ----------------
__device__ __forceinline__ void warp_sum3(float& p0, float& p1, float& p2) {
    #pragma unroll
    for (int o = 16; o > 0; o >>= 1) {
        p0 += __shfl_xor_sync(0xffffffffu, p0, o);
        p1 += __shfl_xor_sync(0xffffffffu, p1, o);
        p2 += __shfl_xor_sync(0xffffffffu, p2, o);
    }
}

// ---------------- fused GAT layers (warp per node, prefetch, flat softmax) ----------------
// Max-subtraction dropped: alpha = e^p / sum e^p is shift-invariant and |p| << 88,
// so flat exp accumulation is mathematically identical and branch-free.

// acc/z laid out: element c = lane + 32*i (i=0..5), head = i/2
__device__ __forceinline__ void gat_core192(int n, int lane, const float* __restrict__ att,
                                            float (&acc)[6], float (&z)[3]) {
    const float* pr = g_xr + (size_t)n * HD192;
    float attr[6], xrr[6];
    #pragma unroll
    for (int i = 0; i < 6; i++) {
        int c = lane + 32 * i;
        attr[i] = att[c]; xrr[i] = pr[c]; acc[i] = 0.f;
    }
    float z0 = 0.f, z1 = 0.f, z2 = 0.f;
    int e  = g_rowptr[n];
    int e1 = g_rowptr[n + 1];

    // prefetch first edge (deg >= 1 guaranteed by self loop)
    float xn[6];
    {
        int s = __ldg(&g_col[e]);
        const float* px = g_xl + (size_t)s * HD192;
        #pragma unroll
        for (int i = 0; i < 6; i++) xn[i] = px[lane + 32 * i];
    }
    for (; e < e1; e++) {
        float xv[6];
        #pragma unroll
        for (int i = 0; i < 6; i++) xv[i] = xn[i];
        if (e + 1 < e1) {
            int s = __ldg(&g_col[e + 1]);
            const float* px = g_xl + (size_t)s * HD192;
            #pragma unroll
            for (int i = 0; i < 6; i++) xn[i] = px[lane + 32 * i];
        }
        float p0 = 0.f, p1 = 0.f, p2 = 0.f;
        #pragma unroll
        for (int i = 0; i < 6; i++) {
            float v = xv[i] + xrr[i];
            v = (v > 0.f) ? v : 0.2f * v;
            float pv = attr[i] * v;
            if (i < 2) p0 += pv; else if (i < 4) p1 += pv; else p2 += pv;
        }
        warp_sum3(p0, p1, p2);
        float ez0 = __expf(p0), ez1 = __expf(p1), ez2 = __expf(p2);
        z0 += ez0; z1 += ez1; z2 += ez2;
        acc[0] += xv[0] * ez0; acc[1] += xv[1] * ez0;
        acc[2] += xv[2] * ez1; acc[3] += xv[3] * ez1;
        acc[4] += xv[4] * ez2; acc[5] += xv[5] * ez2;
    }
    z[0] = z0; z[1] = z1; z[2] = z2;
}

__global__ void gat1_kernel(const float* __restrict__ att, const float* __restrict__ b1) {
    __shared__ float sbn[HD192], sbq[HD192];
    int tid = threadIdx.x;
    if (tid < HD192) { sbn[tid] = 0.f; sbq[tid] = 0.f; }
    __syncthreads();
    int lane = tid & 31, wib = tid >> 5;
    int n = blockIdx.x * 8 + wib;
    if (n < NN) {
        float acc[6]; float z[3];
        gat_core192(n, lane, att, acc, z);
        float iz[3] = {1.f / z[0], 1.f / z[1], 1.f / z[2]};
        float* ph = g_h + (size_t)n * HD192;
        #pragma unroll
        for (int i = 0; i < 6; i++) {
            int c = lane + 32 * i;
            float o = acc[i] * iz[i >> 1] + b1[c];
            o = fmaxf(o, 0.f);
            ph[c] = o;
            atomicAdd(&sbn[c], o);
            atomicAdd(&sbq[c], o * o);
        }
    }
    __syncthreads();
    if (tid < HD192) {
        atomicAdd(&g_bnsum[tid], sbn[tid]);
        atomicAdd(&g_bnsq[tid], sbq[tid]);
    }
}

__global__ void bn_prep_kernel(const float* __restrict__ gamma, const float* __restrict__ beta) {
    int c = threadIdx.x;
    if (c < HD192) {
        float mu = g_bnsum[c] * (1.f / NN);
        float var = g_bnsq[c] * (1.f / NN) - mu * mu;
        float s = gamma[c] * rsqrtf(var + EPSBN);
        g_bnscale[c] = s;
        g_bnshift[c] = beta[c] - mu * s;
    }
}

__global__ void gat2_kernel(const float* __restrict__ att, const float* __restrict__ b2,
                            const int* __restrict__ batch) {
    int tid = threadIdx.x;
    int lane = tid & 31, wib = tid >> 5;
    int n = blockIdx.x * 8 + wib;
    if (n >= NN) return;
    float acc[6]; float z[3];
    gat_core192(n, lane, att, acc, z);
    float iz0 = 1.f / z[0], iz1 = 1.f / z[1], iz2 = 1.f / z[2];
    // element c = lane + 32i -> out dim d = c % 64; acc[0,2,4] -> d=lane; acc[1,3,5] -> d=lane+32
    float v0 = (acc[0] * iz0 + acc[2] * iz1 + acc[4] * iz2) * (1.f / 3.f) + b2[lane];
    float v1 = (acc[1] * iz0 + acc[3] * iz1 + acc[5] * iz2) * (1.f / 3.f) + b2[lane + 32];
    float* ph2 = g_h2 + (size_t)n * D64;
    ph2[lane] = v0;
    ph2[lane + 32] = v1;
    int b = batch[n];
    atomicAdd(&g_pool[b * D64 + lane], v0);
    atomicAdd(&g_pool[b * D64 + lane + 32], v1);
    if (lane == 0) atomicAdd(&g_cnt[b], 1.f);
}

// layer 3: rows stride HD63, prefetch, flat softmax
__global__ void gat3_kernel(const float* __restrict__ att, const float* __restrict__ b3,
                            float* __restrict__ out) {
    __shared__ float sh[8][64];
    int tid = threadIdx.x;
    int lane = tid & 31, wib = tid >> 5;
    int n = blockIdx.x * 8 + wib;
    if (n >= NN) return;
    int c0 = lane, c1 = lane + 32;
    int h0 = c0 / D21;                     // 0 or 1
    int h1 = c1 / D21;                     // 1 or 2 (c1 < 63)
    bool v1ok = (c1 < HD63);
    float attr0 = att[c0], attr1 = v1ok ? att[c1] : 0.f;
    const float* pr = g_xr + (size_t)n * HD63;
    float xr0 = pr[c0], xr1 = v1ok ? pr[c1] : 0.f;
    float a0 = 0.f, a1 = 0.f;
    float z0 = 0.f, z1 = 0.f, z2 = 0.f;
    int e  = g_rowptr[n];
    int e1 = g_rowptr[n + 1];

    float xn0, xn1;
    {
        int s = __ldg(&g_col[e]);
        const float* px = g_xl + (size_t)s * HD63;
        xn0 = px[c0];
        xn1 = v1ok ? px[c1] : 0.f;
    }
    for (; e < e1; e++) {
        float x0 = xn0, x1 = xn1;
        if (e + 1 < e1) {
            int s = __ldg(&g_col[e + 1]);
            const float* px = g_xl + (size_t)s * HD63;
            xn0 = px[c0];
            xn1 = v1ok ? px[c1] : 0.f;
        }
        float t0 = x0 + xr0; t0 = (t0 > 0.f) ? t0 : 0.2f * t0;
        float t1 = x1 + xr1; t1 = (t1 > 0.f) ? t1 : 0.2f * t1;
        float q0 = attr0 * t0, q1 = attr1 * t1;
        float p0 = (h0 == 0) ? q0 : 0.f;
        float p1 = ((h0 == 1) ? q0 : 0.f) + ((h1 == 1) ? q1 : 0.f);
        float p2 = (h1 == 2) ? q1 : 0.f;
        warp_sum3(p0, p1, p2);
        float ez0 = __expf(p0), ez1 = __expf(p1), ez2 = __expf(p2);
        z0 += ez0; z1 += ez1; z2 += ez2;
        a0 += x0 * ((h0 == 0) ? ez0 : ez1);
        a1 += x1 * ((h1 == 1) ? ez1 : ez2);
    }
    float iz0 = 1.f / z0, iz1 = 1.f / z1, iz2 = 1.f / z2;
    sh[wib][c0] = a0 * ((h0 == 0) ? iz0 : iz1);
    if (v1ok) sh[wib][c1] = a1 * ((h1 == 1) ? iz1 : iz2);
    __syncwarp();
    if (lane < D21) {
        float o = (sh[wib][lane] + sh[wib][lane + D21] + sh[wib][lane + 2 * D21]) * (1.f / 3.f)
                  + b3[lane];
        out[NG * NCLS + (size_t)n * D21 + lane] = o;
    }
}

__global__ void classifier_kernel(const float* __restrict__ Wc, const float* __restrict__ bc,
                                  float* __restrict__ out) {
    int t = threadIdx.x;
    if (t >= NG * NCLS) return;
    int g = t / NCLS, j = t % NCLS;
    float cnt = fmaxf(g_cnt[g], 1.f);
    float s = bc[j];
    #pragma unroll
    for (int d = 0; d < D64; d++)
        s += (g_pool[g * D64 + d] / cnt) * Wc[d * NCLS + j];
    out[t] = s;
}

// ---------------- launch (single stream, fully serial) ----------------
extern "C" void kernel_launch(void* const* d_in, const int* in_sizes, int n_in,
                              void* d_out, int out_size) {
    const float* x     = (const float*)d_in[0];
    const int*   ei    = (const int*)d_in[1];
    const int*   batch = (const int*)d_in[2];
    const float* Wl1   = (const float*)d_in[3];
    const float* Wr1   = (const float*)d_in[4];
    const float* att1  = (const float*)d_in[5];
    const float* b1    = (const float*)d_in[6];
    const float* gamma = (const float*)d_in[7];
    const float* beta  = (const float*)d_in[8];
    const float* Wl2   = (const float*)d_in[9];
    const float* Wr2   = (const float*)d_in[10];
    const float* att2  = (const float*)d_in[11];
    const float* b2    = (const float*)d_in[12];
    const float* Wl3   = (const float*)d_in[13];
    const float* Wr3   = (const float*)d_in[14];
    const float* att3  = (const float*)d_in[15];
    const float* b3    = (const float*)d_in[16];
    const float* Wc    = (const float*)d_in[17];
    const float* bc    = (const float*)d_in[18];
    float* out = (float*)d_out;

    const int* src  = ei;
    const int* dstp = ei + NE;

    float *pxl, *pxr, *ph, *ph2;
    cudaGetSymbolAddress((void**)&pxl, g_xl);
    cudaGetSymbolAddress((void**)&pxr, g_xr);
    cudaGetSymbolAddress((void**)&ph,  g_h);
    cudaGetSymbolAddress((void**)&ph2, g_h2);

    auto smem_for = [](int K) { return (size_t)(64 * (K + 4) + 32 * SAS) * 4; };
    static bool attr_set = false;
    if (!attr_set) {
        cudaFuncSetAttribute(gemm_tf32_kernel,
                             cudaFuncAttributeMaxDynamicSharedMemorySize,
                             (int)smem_for(HD192));
        attr_set = true;
    }

    reset_small_kernel<<<1, 512>>>();

    // CSR build (reused by all three layers)
    init_counts_kernel<<<(NN + 255) / 256, 256>>>();
    hist_kernel<<<(NE + 255) / 256, 256>>>(dstp);
    scan1_kernel<<<SBLK, 256>>>();
    scan2_kernel<<<1, 128>>>();
    scan3_kernel<<<SBLK, 256>>>();
    csr_fill_kernel<<<(ETOT + 255) / 256, 256>>>(src, dstp);

    const int gat_grid = (NN + 7) / 8;
    const int my = (NN + 127) / 128;

    // ---- layer 1: x(128) -> 3x64 concat ----
    {
        dim3 g(3, my, 2);
        gemm_tf32_kernel<<<g, 256, smem_for(128)>>>(x, Wl1, Wr1, pxl, pxr, NN, HD192, 128, HD192, 0);
    }
    gat1_kernel<<<gat_grid, 256>>>(att1, b1);
    bn_prep_kernel<<<1, 256>>>(gamma, beta);

    // ---- layer 2: BN(h)(192) -> 64 (head mean), + pooling ----
    {
        dim3 g(3, my, 2);
        gemm_tf32_kernel<<<g, 256, smem_for(HD192)>>>(ph, Wl2, Wr2, pxl, pxr, NN, HD192, HD192, HD192, 2);
    }
    gat2_kernel<<<gat_grid, 256>>>(att2, b2, batch);
    classifier_kernel<<<1, 128>>>(Wc, bc, out);

    // ---- layer 3: relu(h2)(64) -> 21 (head mean), rows stride HD63 ----
    {
        dim3 g(1, my, 2);
        gemm_tf32_kernel<<<g, 256, smem_for(D64)>>>(ph2, Wl3, Wr3, pxl, pxr, NN, HD63, D64, HD63, 1);
    }
    gat3_kernel<<<gat_grid, 256>>>(att3, b3, out);
}